// round 7
// baseline (speedup 1.0000x reference)
#include <cuda_runtime.h>
#include <cstdint>

// EvroModel: x[131072,256] -> relu(x@w1+b1)[.,64] -> tanh(@w2+b2)[.,16] -> @w3+b3 [.,4]
// -> softmax over the ENTIRE flattened tensor.
//
// Round 7: 3xTF32 mma.sync GEMM with
//  (a) A operand staged gmem->smem via 4-stage cp.async pipeline (3 slabs in
//      flight) -> DRAM latency fully decoupled from the MMA stream
//  (b) term-major MMA ordering over nt-pairs -> same-accumulator dependency
//      distance 4 (was 1), hiding HMMA latency
//  (c) packed bank-swizzled B frags (1 LDS.128 per (kt,nt)), as Round 6.

#define B_ROWS   131072
#define ROWS_CTA 512
#define NBLK     (B_ROWS / ROWS_CTA)   // 256
#define TPB      512
#define KDIM     256
#define H1_PITCH 68
#define STAGES   4

// byte offsets in dynamic smem
#define SB_OFF     0                   // packed B frags: 131072 B
#define SX_OFF     131072              // 4 stages x 16384 B = 65536 B
#define STAGE_B    16384
// float offsets
#define H1_OFF_F   0                   // ALIAS over sB+SX after GEMM (512x68 fl)
#define W2_OFF_F   49152               // 64 x 16
#define B1_OFF_F   50176               // 64
#define B2_OFF_F   50240               // 16
#define W3_OFF_F   50256               // 16 x 4
#define B3_OFF_F   50320               // 4
#define RED_OFF_F  50324               // 512
#define SM_FLOATS  50836               // 203344 B

__device__ float g_partials[NBLK];
__device__ float g_inv_sum;

__device__ __forceinline__ uint32_t f2tf32(float v) {
    uint32_t u;
    asm("cvt.rna.tf32.f32 %0, %1;" : "=r"(u) : "f"(v));
    return u;
}
__device__ __forceinline__ uint32_t smem_u32(const void* p) {
    uint32_t a;
    asm("{ .reg .u64 t; cvta.to.shared.u64 t, %1; cvt.u32.u64 %0, t; }" : "=r"(a) : "l"(p));
    return a;
}
__device__ __forceinline__ void lds128(uint32_t r[4], uint32_t addr) {
    asm volatile("ld.shared.v4.b32 {%0,%1,%2,%3}, [%4];"
                 : "=r"(r[0]), "=r"(r[1]), "=r"(r[2]), "=r"(r[3]) : "r"(addr));
}
__device__ __forceinline__ float2 lds64f(uint32_t addr) {
    float2 v;
    asm volatile("ld.shared.v2.f32 {%0,%1}, [%2];" : "=f"(v.x), "=f"(v.y) : "r"(addr));
    return v;
}
__device__ __forceinline__ void cp16(uint32_t saddr, const void* gaddr) {
    asm volatile("cp.async.cg.shared.global [%0], [%1], 16;" :: "r"(saddr), "l"(gaddr));
}
#define CP_COMMIT() asm volatile("cp.async.commit_group;" ::: "memory")
#define CP_WAIT2()  asm volatile("cp.async.wait_group 2;" ::: "memory")

__device__ __forceinline__ void mma_tf32(float c[4], const uint32_t a[4],
                                         uint32_t b0, uint32_t b1) {
    asm("mma.sync.aligned.m16n8k8.row.col.f32.tf32.tf32.f32 "
        "{%0,%1,%2,%3}, {%4,%5,%6,%7}, {%8,%9}, {%0,%1,%2,%3};"
        : "+f"(c[0]), "+f"(c[1]), "+f"(c[2]), "+f"(c[3])
        : "r"(a[0]), "r"(a[1]), "r"(a[2]), "r"(a[3]), "r"(b0), "r"(b1));
}

__global__ __launch_bounds__(TPB, 1)
void mlp_kernel(const float* __restrict__ x,
                const float* __restrict__ w1, const float* __restrict__ b1,
                const float* __restrict__ w2, const float* __restrict__ b2,
                const float* __restrict__ w3, const float* __restrict__ b3,
                float* __restrict__ out)
{
    extern __shared__ float sm[];
    uint32_t* sB  = (uint32_t*)((char*)sm + SB_OFF);
    float*    sh1 = sm + H1_OFF_F;     // aliases sB/SX after the GEMM

    const int tid = threadIdx.x;
    const int wid = tid >> 5;
    const int lane = tid & 31;
    const int g = lane >> 2;       // 0..7
    const int tig = lane & 3;      // 0..3

    const uint32_t smb = smem_u32(sm);
    const uint32_t sx_base = smb + SX_OFF;

    // ---- kick off A pipeline: slabs 0..STAGES-2 ----
    // slab j: 512 rows x 8 k fp32; thread copies its own row (tid), 2x16B
    const char* xrow = (const char*)(x + ((size_t)blockIdx.x * ROWS_CTA + tid) * KDIM);
    #pragma unroll
    for (int s = 0; s < STAGES - 1; s++) {
        uint32_t dst = sx_base + (uint32_t)(s * STAGE_B + tid * 32);
        cp16(dst,      xrow + s * 32);
        cp16(dst + 16, xrow + s * 32 + 16);
        CP_COMMIT();
    }

    // ---- stage w1 as packed tf32 hi/lo B-fragments (as Round 6) ----
    for (int e = tid; e < 16384; e += TPB) {
        int k = e >> 6, n = e & 63;
        float v = w1[e];
        uint32_t hi = f2tf32(v);
        uint32_t lo = f2tf32(v - __uint_as_float(hi));
        int b = k >> 3, m = k & 7;
        int t = m >> 1, j = m & 1;
        int nt = n >> 3, gg = n & 7;
        int q = (t + gg) & 3;
        uint32_t base = (uint32_t)((((b * 8 + nt) * 8 + gg) * 4 + q) * 4);
        sB[base + j] = hi;
        sB[base + 2 + j] = lo;
    }
    {
        float* sw2 = sm + W2_OFF_F;
        for (int i = tid; i < 1024; i += TPB) sw2[i] = w2[i];
        if (tid < 64) sm[B1_OFF_F + tid] = b1[tid];
        if (tid < 16) sm[B2_OFF_F + tid] = b2[tid];
        if (tid < 64) sm[W3_OFF_F + tid] = w3[tid];
        if (tid < 4)  sm[B3_OFF_F + tid] = b3[tid];
    }
    __syncthreads();

    const uint32_t sB_addr = smb + SB_OFF;
    const uint32_t b_lane_off = (uint32_t)((g * 4 + ((tig + g) & 3)) * 16);
    // A frag smem offsets within a slab (row stride 32B)
    const uint32_t a_off0 = (uint32_t)((wid * 32 + g) * 32 + tig * 8);

    float c[2][8][4];
    #pragma unroll
    for (int mt = 0; mt < 2; mt++)
        #pragma unroll
        for (int nt = 0; nt < 8; nt++)
            #pragma unroll
            for (int r = 0; r < 4; r++) c[mt][nt][r] = 0.0f;

    #pragma unroll 1
    for (int kt = 0; kt < 32; kt++) {
        CP_WAIT2();            // slab kt's data (this thread) complete
        __syncthreads();       // everyone's slab kt ready; stage (kt-1)%4 free

        // issue load of slab kt+3 into the freed stage
        if (kt + STAGES - 1 < 32) {
            int j = kt + STAGES - 1;
            uint32_t dst = sx_base + (uint32_t)((j & (STAGES - 1)) * STAGE_B + tid * 32);
            cp16(dst,      xrow + j * 32);
            cp16(dst + 16, xrow + j * 32 + 16);
        }
        CP_COMMIT();           // one group per iteration (possibly empty)

        // ---- load A frags from slab kt, split hi/lo ----
        const uint32_t sa = sx_base + (uint32_t)((kt & (STAGES - 1)) * STAGE_B);
        uint32_t ah[2][4], al[2][4];
        #pragma unroll
        for (int mt = 0; mt < 2; mt++) {
            float2 r0 = lds64f(sa + a_off0 + (uint32_t)(mt * 16 * 32));
            float2 r1 = lds64f(sa + a_off0 + (uint32_t)((mt * 16 + 8) * 32));
            // frag: a0=(row g, k tig)=r0.x  a1=(row g+8)=r1.x  a2=(row g, k tig+4)=r0.y  a3=r1.y
            ah[mt][0] = f2tf32(r0.x); al[mt][0] = f2tf32(r0.x - __uint_as_float(ah[mt][0]));
            ah[mt][1] = f2tf32(r1.x); al[mt][1] = f2tf32(r1.x - __uint_as_float(ah[mt][1]));
            ah[mt][2] = f2tf32(r0.y); al[mt][2] = f2tf32(r0.y - __uint_as_float(ah[mt][2]));
            ah[mt][3] = f2tf32(r1.y); al[mt][3] = f2tf32(r1.y - __uint_as_float(ah[mt][3]));
        }

        // ---- B frags: nt-pairs, term-major (dependency distance 4) ----
        const uint32_t kt_base = sB_addr + (uint32_t)(kt * 8 * 512) + b_lane_off;
        uint32_t b0[4], b1[4], p0[4], p1[4];
        lds128(b0, kt_base);
        lds128(b1, kt_base + 512);
        #pragma unroll
        for (int ntp = 0; ntp < 4; ntp++) {
            if (ntp < 3) {
                lds128(p0, kt_base + (uint32_t)((2 * ntp + 2) * 512));
                lds128(p1, kt_base + (uint32_t)((2 * ntp + 3) * 512));
            }
            const int n0 = 2 * ntp, n1 = 2 * ntp + 1;
            // term hh
            mma_tf32(c[0][n0], ah[0], b0[0], b0[1]);
            mma_tf32(c[1][n0], ah[1], b0[0], b0[1]);
            mma_tf32(c[0][n1], ah[0], b1[0], b1[1]);
            mma_tf32(c[1][n1], ah[1], b1[0], b1[1]);
            // term hl
            mma_tf32(c[0][n0], ah[0], b0[2], b0[3]);
            mma_tf32(c[1][n0], ah[1], b0[2], b0[3]);
            mma_tf32(c[0][n1], ah[0], b1[2], b1[3]);
            mma_tf32(c[1][n1], ah[1], b1[2], b1[3]);
            // term lh
            mma_tf32(c[0][n0], al[0], b0[0], b0[1]);
            mma_tf32(c[1][n0], al[1], b0[0], b0[1]);
            mma_tf32(c[0][n1], al[0], b1[0], b1[1]);
            mma_tf32(c[1][n1], al[1], b1[0], b1[1]);
            #pragma unroll
            for (int s = 0; s < 4; s++) { b0[s] = p0[s]; b1[s] = p1[s]; }
        }
    }

    // ---- sB/SX dead; alias with h1 and write C frags ----
    __syncthreads();
    #pragma unroll
    for (int mt = 0; mt < 2; mt++) {
        int row0 = wid * 32 + mt * 16 + g;
        #pragma unroll
        for (int nt = 0; nt < 8; nt++) {
            int col = nt * 8 + tig * 2;
            float2 v0; v0.x = c[mt][nt][0]; v0.y = c[mt][nt][1];
            float2 v1; v1.x = c[mt][nt][2]; v1.y = c[mt][nt][3];
            *(float2*)&sh1[row0 * H1_PITCH + col] = v0;
            *(float2*)&sh1[(row0 + 8) * H1_PITCH + col] = v1;
        }
    }
    __syncthreads();

    // ---- per-thread fp32 tail: row = tid ----
    const float* sb1 = sm + B1_OFF_F;
    const float* sw2 = sm + W2_OFF_F;
    const float* sb2 = sm + B2_OFF_F;
    const float* sw3 = sm + W3_OFF_F;
    const float* sb3 = sm + B3_OFF_F;
    const float* hrow = &sh1[tid * H1_PITCH];

    float h2[16];
    #pragma unroll
    for (int j = 0; j < 16; j++) h2[j] = sb2[j];
    #pragma unroll
    for (int i4 = 0; i4 < 16; i4++) {
        float4 hv = *(const float4*)&hrow[i4 * 4];
        float h0 = fmaxf(hv.x + sb1[i4 * 4 + 0], 0.0f);
        float h1v = fmaxf(hv.y + sb1[i4 * 4 + 1], 0.0f);
        float h2v = fmaxf(hv.z + sb1[i4 * 4 + 2], 0.0f);
        float h3 = fmaxf(hv.w + sb1[i4 * 4 + 3], 0.0f);
        const float* wr0 = &sw2[(i4 * 4 + 0) * 16];
        const float* wr1 = &sw2[(i4 * 4 + 1) * 16];
        const float* wr2 = &sw2[(i4 * 4 + 2) * 16];
        const float* wr3 = &sw2[(i4 * 4 + 3) * 16];
        #pragma unroll
        for (int j = 0; j < 16; j++) {
            float t = fmaf(h0, wr0[j], h2[j]);
            t = fmaf(h1v, wr1[j], t);
            t = fmaf(h2v, wr2[j], t);
            h2[j] = fmaf(h3, wr3[j], t);
        }
    }
    #pragma unroll
    for (int j = 0; j < 16; j++) h2[j] = tanhf(h2[j]);

    float lg[4];
    #pragma unroll
    for (int j = 0; j < 4; j++) lg[j] = sb3[j];
    #pragma unroll
    for (int i = 0; i < 16; i++) {
        float h = h2[i];
        const float* wr = &sw3[i * 4];
        #pragma unroll
        for (int j = 0; j < 4; j++) lg[j] = fmaf(h, wr[j], lg[j]);
    }

    float e0 = __expf(lg[0]);
    float e1 = __expf(lg[1]);
    float e2 = __expf(lg[2]);
    float e3 = __expf(lg[3]);

    const size_t row = (size_t)blockIdx.x * ROWS_CTA + tid;
    float4 ev; ev.x = e0; ev.y = e1; ev.z = e2; ev.w = e3;
    ((float4*)out)[row] = ev;

    // deterministic block partial sum
    float* red = sm + RED_OFF_F;
    red[tid] = (e0 + e1) + (e2 + e3);
    __syncthreads();
    #pragma unroll
    for (int off = TPB / 2; off > 0; off >>= 1) {
        if (tid < off) red[tid] += red[tid + off];
        __syncthreads();
    }
    if (tid == 0) g_partials[blockIdx.x] = red[0];
}

__global__ void reduce_kernel()
{
    __shared__ float red[NBLK];
    const int tid = threadIdx.x;
    red[tid] = g_partials[tid];
    __syncthreads();
    #pragma unroll
    for (int off = NBLK / 2; off > 0; off >>= 1) {
        if (tid < off) red[tid] += red[tid + off];
        __syncthreads();
    }
    if (tid == 0) g_inv_sum = 1.0f / red[0];
}

__global__ void scale_kernel(float* __restrict__ out)
{
    const int i = blockIdx.x * blockDim.x + threadIdx.x;  // one float4 per thread
    const float inv = g_inv_sum;
    float4 v = ((float4*)out)[i];
    v.x *= inv; v.y *= inv; v.z *= inv; v.w *= inv;
    ((float4*)out)[i] = v;
}

extern "C" void kernel_launch(void* const* d_in, const int* in_sizes, int n_in,
                              void* d_out, int out_size)
{
    const float* x  = (const float*)d_in[0];
    const float* w1 = (const float*)d_in[1];
    const float* b1 = (const float*)d_in[2];
    const float* w2 = (const float*)d_in[3];
    const float* b2 = (const float*)d_in[4];
    const float* w3 = (const float*)d_in[5];
    const float* b3 = (const float*)d_in[6];
    float* out = (float*)d_out;

    const size_t smem = SM_FLOATS * sizeof(float);
    cudaFuncSetAttribute(mlp_kernel, cudaFuncAttributeMaxDynamicSharedMemorySize, (int)smem);

    mlp_kernel<<<NBLK, TPB, smem>>>(x, w1, b1, w2, b2, w3, b3, out);
    reduce_kernel<<<1, NBLK>>>();
    scale_kernel<<<(B_ROWS * 4) / (4 * 256), 256>>>(out);
}

// round 8
// speedup vs baseline: 1.2355x; 1.2355x over previous
#include <cuda_runtime.h>
#include <cstdint>

// EvroModel: x[131072,256] -> relu(x@w1+b1)[.,64] -> tanh(@w2+b2)[.,16] -> @w3+b3 [.,4]
// -> softmax over the ENTIRE flattened tensor.
//
// Round 8: persistent 3xTF32 mma.sync GEMM.
//  - grid=148 (1 CTA/SM), 1024 chunks of 128 rows, strided chunk ownership
//    -> kills the 1.73-wave quantization loss of grid=256
//  - warp tile = 16 rows x 32 cols (1 m-tile, 4 nt); 16 warps/CTA
//  - term-major MMA order: same-accumulator dependency distance 4
//  - depth-2 per-warp register prefetch of A, NO barriers in the k-loop
//  - packed bank-swizzled B frags (1 LDS.128 per (kt,nt)), staged once per CTA

#define B_ROWS   131072
#define CHUNK    128
#define NCHUNKS  (B_ROWS / CHUNK)      // 1024
#define GRID     148
#define TPB      512
#define KDIM     256
#define H1_PITCH 68

// float offsets in dynamic smem
#define SB_OFF_B   0                   // packed B frags: 32768 u32 = 131072 B
#define H1_OFF_F   32768               // 128 x 68 floats
#define W2_OFF_F   41472               // 64 x 16
#define B1_OFF_F   42496               // 64
#define B2_OFF_F   42560               // 16
#define W3_OFF_F   42576               // 16 x 4
#define B3_OFF_F   42640               // 4
#define RED_OFF_F  42644               // 128
#define SM_FLOATS  42772               // 171088 B

__device__ float g_partials[NCHUNKS];
__device__ float g_inv_sum;

__device__ __forceinline__ uint32_t f2tf32(float v) {
    uint32_t u;
    asm("cvt.rna.tf32.f32 %0, %1;" : "=r"(u) : "f"(v));
    return u;
}
__device__ __forceinline__ uint32_t smem_u32(const void* p) {
    uint32_t a;
    asm("{ .reg .u64 t; cvta.to.shared.u64 t, %1; cvt.u32.u64 %0, t; }" : "=r"(a) : "l"(p));
    return a;
}
__device__ __forceinline__ void lds128(uint32_t r[4], uint32_t addr) {
    asm volatile("ld.shared.v4.b32 {%0,%1,%2,%3}, [%4];"
                 : "=r"(r[0]), "=r"(r[1]), "=r"(r[2]), "=r"(r[3]) : "r"(addr));
}
__device__ __forceinline__ void mma_tf32(float c[4], const uint32_t a[4],
                                         uint32_t b0, uint32_t b1) {
    asm("mma.sync.aligned.m16n8k8.row.col.f32.tf32.tf32.f32 "
        "{%0,%1,%2,%3}, {%4,%5,%6,%7}, {%8,%9}, {%0,%1,%2,%3};"
        : "+f"(c[0]), "+f"(c[1]), "+f"(c[2]), "+f"(c[3])
        : "r"(a[0]), "r"(a[1]), "r"(a[2]), "r"(a[3]), "r"(b0), "r"(b1));
}

__global__ __launch_bounds__(TPB, 1)
void mlp_kernel(const float* __restrict__ x,
                const float* __restrict__ w1, const float* __restrict__ b1,
                const float* __restrict__ w2, const float* __restrict__ b2,
                const float* __restrict__ w3, const float* __restrict__ b3,
                float* __restrict__ out)
{
    extern __shared__ float sm[];
    uint32_t* sB  = (uint32_t*)sm;
    float*    sh1 = sm + H1_OFF_F;

    const int tid = threadIdx.x;
    const int wid = tid >> 5;
    const int lane = tid & 31;
    const int g = lane >> 2;       // 0..7
    const int tig = lane & 3;      // 0..3
    const int mt8 = wid & 7;       // m-tile within chunk (16 rows)
    const int nh = wid >> 3;       // n-half (4 nt each)

    // ---- stage w1 as packed tf32 hi/lo B-fragments (layout proven in R6) ----
    for (int e = tid; e < 16384; e += TPB) {
        int k = e >> 6, n = e & 63;
        float v = w1[e];
        uint32_t hi = f2tf32(v);
        uint32_t lo = f2tf32(v - __uint_as_float(hi));
        int b = k >> 3, m = k & 7;
        int t = m >> 1, j = m & 1;
        int nt = n >> 3, gg = n & 7;
        int q = (t + gg) & 3;
        uint32_t base = (uint32_t)((((b * 8 + nt) * 8 + gg) * 4 + q) * 4);
        sB[base + j] = hi;
        sB[base + 2 + j] = lo;
    }
    {
        float* sw2 = sm + W2_OFF_F;
        for (int i = tid; i < 1024; i += TPB) sw2[i] = w2[i];
        if (tid < 64) sm[B1_OFF_F + tid] = b1[tid];
        if (tid < 16) sm[B2_OFF_F + tid] = b2[tid];
        if (tid < 64) sm[W3_OFF_F + tid] = w3[tid];
        if (tid < 4)  sm[B3_OFF_F + tid] = b3[tid];
    }
    __syncthreads();

    const uint32_t sB_addr = smem_u32(sB);
    const uint32_t b_base = sB_addr + (uint32_t)(nh * 2048 + (g * 4 + ((tig + g) & 3)) * 16);

    const float* sb1 = sm + B1_OFF_F;
    const float* sw2 = sm + W2_OFF_F;
    const float* sb2 = sm + B2_OFF_F;
    const float* sw3 = sm + W3_OFF_F;
    const float* sb3 = sm + B3_OFF_F;
    float* red = sm + RED_OFF_F;

    // ---- persistent chunk loop ----
    for (int blk = blockIdx.x; blk < NCHUNKS; blk += GRID) {
        // A pointers for this warp's m-tile (k-permuted float2 loads)
        const float* xr0 = x + ((size_t)blk * CHUNK + mt8 * 16 + g) * KDIM + 2 * tig;
        const float* xr1 = xr0 + 8 * KDIM;

        float c[4][4];
        #pragma unroll
        for (int nt = 0; nt < 4; nt++)
            #pragma unroll
            for (int r = 0; r < 4; r++) c[nt][r] = 0.0f;

        // depth-2 A prefetch
        float2 abuf[2][2];
        abuf[0][0] = __ldg((const float2*)xr0);
        abuf[0][1] = __ldg((const float2*)xr1);
        abuf[1][0] = __ldg((const float2*)(xr0 + 8));
        abuf[1][1] = __ldg((const float2*)(xr1 + 8));

        #pragma unroll 2
        for (int kt = 0; kt < 32; kt++) {
            float2 r0 = abuf[kt & 1][0];
            float2 r1 = abuf[kt & 1][1];
            if (kt + 2 < 32) {
                abuf[kt & 1][0] = __ldg((const float2*)(xr0 + (kt + 2) * 8));
                abuf[kt & 1][1] = __ldg((const float2*)(xr1 + (kt + 2) * 8));
            }

            // split A into tf32 hi/lo (frag a0=row g,k tig; a1=row g+8; a2=k tig+4; a3)
            uint32_t ah[4], al[4];
            ah[0] = f2tf32(r0.x); al[0] = f2tf32(r0.x - __uint_as_float(ah[0]));
            ah[1] = f2tf32(r1.x); al[1] = f2tf32(r1.x - __uint_as_float(ah[1]));
            ah[2] = f2tf32(r0.y); al[2] = f2tf32(r0.y - __uint_as_float(ah[2]));
            ah[3] = f2tf32(r1.y); al[3] = f2tf32(r1.y - __uint_as_float(ah[3]));

            // B frags: 4 independent LDS.128
            const uint32_t kt_base = b_base + (uint32_t)(kt * 4096);
            uint32_t bb0[4], bb1[4], bb2[4], bb3[4];
            lds128(bb0, kt_base);
            lds128(bb1, kt_base + 512);
            lds128(bb2, kt_base + 1024);
            lds128(bb3, kt_base + 1536);

            // term-major MMA: same-accumulator dependency distance 4
            mma_tf32(c[0], ah, bb0[0], bb0[1]);
            mma_tf32(c[1], ah, bb1[0], bb1[1]);
            mma_tf32(c[2], ah, bb2[0], bb2[1]);
            mma_tf32(c[3], ah, bb3[0], bb3[1]);
            mma_tf32(c[0], ah, bb0[2], bb0[3]);
            mma_tf32(c[1], ah, bb1[2], bb1[3]);
            mma_tf32(c[2], ah, bb2[2], bb2[3]);
            mma_tf32(c[3], ah, bb3[2], bb3[3]);
            mma_tf32(c[0], al, bb0[0], bb0[1]);
            mma_tf32(c[1], al, bb1[0], bb1[1]);
            mma_tf32(c[2], al, bb2[0], bb2[1]);
            mma_tf32(c[3], al, bb3[0], bb3[1]);
        }

        // ---- epilogue: C frags -> sh1, then fp32 tail on threads 0..127 ----
        __syncthreads();   // previous chunk's tail is done reading sh1/red
        {
            int row0 = mt8 * 16 + g;
            #pragma unroll
            for (int nt = 0; nt < 4; nt++) {
                int col = nh * 32 + nt * 8 + tig * 2;
                float2 v0; v0.x = c[nt][0]; v0.y = c[nt][1];
                float2 v1; v1.x = c[nt][2]; v1.y = c[nt][3];
                *(float2*)&sh1[row0 * H1_PITCH + col] = v0;
                *(float2*)&sh1[(row0 + 8) * H1_PITCH + col] = v1;
            }
        }
        __syncthreads();

        if (tid < CHUNK) {
            const float* hrow = &sh1[tid * H1_PITCH];
            float h2[16];
            #pragma unroll
            for (int j = 0; j < 16; j++) h2[j] = sb2[j];
            #pragma unroll
            for (int i4 = 0; i4 < 16; i4++) {
                float4 hv = *(const float4*)&hrow[i4 * 4];
                float h0 = fmaxf(hv.x + sb1[i4 * 4 + 0], 0.0f);
                float h1v = fmaxf(hv.y + sb1[i4 * 4 + 1], 0.0f);
                float h2v = fmaxf(hv.z + sb1[i4 * 4 + 2], 0.0f);
                float h3 = fmaxf(hv.w + sb1[i4 * 4 + 3], 0.0f);
                const float* wr0 = &sw2[(i4 * 4 + 0) * 16];
                const float* wr1 = &sw2[(i4 * 4 + 1) * 16];
                const float* wr2 = &sw2[(i4 * 4 + 2) * 16];
                const float* wr3 = &sw2[(i4 * 4 + 3) * 16];
                #pragma unroll
                for (int j = 0; j < 16; j++) {
                    float t = fmaf(h0, wr0[j], h2[j]);
                    t = fmaf(h1v, wr1[j], t);
                    t = fmaf(h2v, wr2[j], t);
                    h2[j] = fmaf(h3, wr3[j], t);
                }
            }
            #pragma unroll
            for (int j = 0; j < 16; j++) h2[j] = tanhf(h2[j]);

            float lg[4];
            #pragma unroll
            for (int j = 0; j < 4; j++) lg[j] = sb3[j];
            #pragma unroll
            for (int i = 0; i < 16; i++) {
                float h = h2[i];
                const float* wr = &sw3[i * 4];
                #pragma unroll
                for (int j = 0; j < 4; j++) lg[j] = fmaf(h, wr[j], lg[j]);
            }

            float e0 = __expf(lg[0]);
            float e1 = __expf(lg[1]);
            float e2 = __expf(lg[2]);
            float e3 = __expf(lg[3]);

            float4 ev; ev.x = e0; ev.y = e1; ev.z = e2; ev.w = e3;
            ((float4*)out)[(size_t)blk * CHUNK + tid] = ev;
            red[tid] = (e0 + e1) + (e2 + e3);
        }
        __syncthreads();

        // deterministic tree over 128 entries
        #pragma unroll
        for (int off = CHUNK / 2; off > 0; off >>= 1) {
            if (tid < off) red[tid] += red[tid + off];
            __syncthreads();
        }
        if (tid == 0) g_partials[blk] = red[0];
    }
}

__global__ void reduce_kernel()
{
    __shared__ float red[NCHUNKS];
    const int tid = threadIdx.x;
    red[tid] = g_partials[tid];
    __syncthreads();
    #pragma unroll
    for (int off = NCHUNKS / 2; off > 0; off >>= 1) {
        if (tid < off) red[tid] += red[tid + off];
        __syncthreads();
    }
    if (tid == 0) g_inv_sum = 1.0f / red[0];
}

__global__ void scale_kernel(float* __restrict__ out)
{
    const int i = blockIdx.x * blockDim.x + threadIdx.x;  // one float4 per thread
    const float inv = g_inv_sum;
    float4 v = ((float4*)out)[i];
    v.x *= inv; v.y *= inv; v.z *= inv; v.w *= inv;
    ((float4*)out)[i] = v;
}

extern "C" void kernel_launch(void* const* d_in, const int* in_sizes, int n_in,
                              void* d_out, int out_size)
{
    const float* x  = (const float*)d_in[0];
    const float* w1 = (const float*)d_in[1];
    const float* b1 = (const float*)d_in[2];
    const float* w2 = (const float*)d_in[3];
    const float* b2 = (const float*)d_in[4];
    const float* w3 = (const float*)d_in[5];
    const float* b3 = (const float*)d_in[6];
    float* out = (float*)d_out;

    const size_t smem = SM_FLOATS * sizeof(float);
    cudaFuncSetAttribute(mlp_kernel, cudaFuncAttributeMaxDynamicSharedMemorySize, (int)smem);

    mlp_kernel<<<GRID, TPB, smem>>>(x, w1, b1, w2, b2, w3, b3, out);
    reduce_kernel<<<1, NCHUNKS>>>();
    scale_kernel<<<(B_ROWS * 4) / (4 * 256), 256>>>(out);
}

// round 9
// speedup vs baseline: 1.3771x; 1.1147x over previous
#include <cuda_runtime.h>
#include <cstdint>

// EvroModel: x[131072,256] -> relu(x@w1+b1)[.,64] -> tanh(@w2+b2)[.,16] -> @w3+b3 [.,4]
// -> softmax over the ENTIRE flattened tensor.
//
// Round 9: Round-6 structure (proven 94.7us) with two changes:
//  (a) term-major MMA ordering over nt-pairs x mt -> same-accumulator
//      dependency distance 4 (was 1), hiding HMMA RAW latency
//  (b) reduce_kernel folded into scale_kernel (redundant deterministic
//      per-block reduction of the 256 partials), saving one launch.

#define B_ROWS   131072
#define ROWS_CTA 512
#define NBLK     (B_ROWS / ROWS_CTA)   // 256
#define TPB      512
#define KDIM     256
#define H1_PITCH 68

// dynamic smem layout (floats / bytes)
#define SB_OFF_B   0                   // packed B frags: 32768 u32 = 131072 B
#define H1_OFF_F   0                   // ALIAS over sB after GEMM: 512 x 68 floats
#define W2_OFF_F   34816               // 64 x 16
#define B1_OFF_F   35840               // 64
#define B2_OFF_F   35904               // 16
#define W3_OFF_F   35920               // 16 x 4
#define B3_OFF_F   35984               // 4
#define RED_OFF_F  35988               // 512
#define SM_FLOATS  36500

__device__ float g_partials[NBLK];

__device__ __forceinline__ uint32_t f2tf32(float v) {
    uint32_t u;
    asm("cvt.rna.tf32.f32 %0, %1;" : "=r"(u) : "f"(v));
    return u;
}
__device__ __forceinline__ uint32_t smem_u32(const void* p) {
    uint32_t a;
    asm("{ .reg .u64 t; cvta.to.shared.u64 t, %1; cvt.u32.u64 %0, t; }" : "=r"(a) : "l"(p));
    return a;
}
__device__ __forceinline__ void lds128(uint32_t r[4], uint32_t addr) {
    asm volatile("ld.shared.v4.b32 {%0,%1,%2,%3}, [%4];"
                 : "=r"(r[0]), "=r"(r[1]), "=r"(r[2]), "=r"(r[3]) : "r"(addr));
}
__device__ __forceinline__ void mma_tf32(float c[4], const uint32_t a[4],
                                         uint32_t b0, uint32_t b1) {
    asm("mma.sync.aligned.m16n8k8.row.col.f32.tf32.tf32.f32 "
        "{%0,%1,%2,%3}, {%4,%5,%6,%7}, {%8,%9}, {%0,%1,%2,%3};"
        : "+f"(c[0]), "+f"(c[1]), "+f"(c[2]), "+f"(c[3])
        : "r"(a[0]), "r"(a[1]), "r"(a[2]), "r"(a[3]), "r"(b0), "r"(b1));
}

__global__ __launch_bounds__(TPB, 1)
void mlp_kernel(const float* __restrict__ x,
                const float* __restrict__ w1, const float* __restrict__ b1,
                const float* __restrict__ w2, const float* __restrict__ b2,
                const float* __restrict__ w3, const float* __restrict__ b3,
                float* __restrict__ out)
{
    extern __shared__ float sm[];
    uint32_t* sB  = (uint32_t*)((char*)sm + SB_OFF_B);
    float*    sh1 = sm + H1_OFF_F;     // aliases sB after the GEMM

    const int tid = threadIdx.x;
    const int wid = tid >> 5;
    const int lane = tid & 31;
    const int g = lane >> 2;       // 0..7
    const int tig = lane & 3;      // 0..3

    // ---- stage w1 as packed tf32 hi/lo B-fragments ----
    for (int e = tid; e < 16384; e += TPB) {
        int k = e >> 6, n = e & 63;
        float v = w1[e];
        uint32_t hi = f2tf32(v);
        uint32_t lo = f2tf32(v - __uint_as_float(hi));
        int b = k >> 3, m = k & 7;
        int t = m >> 1, j = m & 1;
        int nt = n >> 3, gg = n & 7;
        int q = (t + gg) & 3;
        uint32_t base = (uint32_t)((((b * 8 + nt) * 8 + gg) * 4 + q) * 4);
        sB[base + j] = hi;
        sB[base + 2 + j] = lo;
    }
    {
        float* sw2 = sm + W2_OFF_F;
        for (int i = tid; i < 1024; i += TPB) sw2[i] = w2[i];
        if (tid < 64) sm[B1_OFF_F + tid] = b1[tid];
        if (tid < 16) sm[B2_OFF_F + tid] = b2[tid];
        if (tid < 64) sm[W3_OFF_F + tid] = w3[tid];
        if (tid < 4)  sm[B3_OFF_F + tid] = b3[tid];
    }
    __syncthreads();

    const uint32_t sB_addr = smem_u32(sB);
    const uint32_t b_lane_off = (uint32_t)((g * 4 + ((tig + g) & 3)) * 16);

    // ---- layer-1 GEMM: warp computes rows [wid*32, wid*32+32), all 64 cols ----
    const float* xb = x + ((size_t)blockIdx.x * ROWS_CTA + wid * 32 + g) * KDIM;

    float c[2][8][4];
    #pragma unroll
    for (int mt = 0; mt < 2; mt++)
        #pragma unroll
        for (int nt = 0; nt < 8; nt++)
            #pragma unroll
            for (int r = 0; r < 4; r++) c[mt][nt][r] = 0.0f;

    // A: float2 at (row, col = kt*8 + 2*tig) gives frag slots (tig, tig+4)
    float2 ra[2][2];   // [mt][row g / row g+8]
    #pragma unroll
    for (int mt = 0; mt < 2; mt++) {
        const float* q = xb + mt * (16 * KDIM) + 2 * tig;
        ra[mt][0] = __ldg((const float2*)q);
        ra[mt][1] = __ldg((const float2*)(q + 8 * KDIM));
    }

    #pragma unroll 1
    for (int kt = 0; kt < 32; kt++) {
        // prefetch next k-tile's A
        float2 rb[2][2];
        if (kt < 31) {
            #pragma unroll
            for (int mt = 0; mt < 2; mt++) {
                const float* q = xb + mt * (16 * KDIM) + (kt + 1) * 8 + 2 * tig;
                rb[mt][0] = __ldg((const float2*)q);
                rb[mt][1] = __ldg((const float2*)(q + 8 * KDIM));
            }
        }

        // split A into tf32 hi/lo (frag order a0..a3)
        uint32_t ah[2][4], al[2][4];
        #pragma unroll
        for (int mt = 0; mt < 2; mt++) {
            float a0 = ra[mt][0].x, a2 = ra[mt][0].y;
            float a1 = ra[mt][1].x, a3 = ra[mt][1].y;
            ah[mt][0] = f2tf32(a0); al[mt][0] = f2tf32(a0 - __uint_as_float(ah[mt][0]));
            ah[mt][1] = f2tf32(a1); al[mt][1] = f2tf32(a1 - __uint_as_float(ah[mt][1]));
            ah[mt][2] = f2tf32(a2); al[mt][2] = f2tf32(a2 - __uint_as_float(ah[mt][2]));
            ah[mt][3] = f2tf32(a3); al[mt][3] = f2tf32(a3 - __uint_as_float(ah[mt][3]));
        }

        // B frags: nt-pairs with double-buffer; term-major MMA (distance 4)
        const uint32_t kt_base = sB_addr + (uint32_t)(kt * 8 * 512) + b_lane_off;
        uint32_t b0[4], b1[4], p0[4], p1[4];
        lds128(b0, kt_base);
        lds128(b1, kt_base + 512);
        #pragma unroll
        for (int ntp = 0; ntp < 4; ntp++) {
            if (ntp < 3) {
                lds128(p0, kt_base + (uint32_t)((2 * ntp + 2) * 512));
                lds128(p1, kt_base + (uint32_t)((2 * ntp + 3) * 512));
            }
            const int n0 = 2 * ntp, n1 = 2 * ntp + 1;
            // term hh
            mma_tf32(c[0][n0], ah[0], b0[0], b0[1]);
            mma_tf32(c[1][n0], ah[1], b0[0], b0[1]);
            mma_tf32(c[0][n1], ah[0], b1[0], b1[1]);
            mma_tf32(c[1][n1], ah[1], b1[0], b1[1]);
            // term hl
            mma_tf32(c[0][n0], ah[0], b0[2], b0[3]);
            mma_tf32(c[1][n0], ah[1], b0[2], b0[3]);
            mma_tf32(c[0][n1], ah[0], b1[2], b1[3]);
            mma_tf32(c[1][n1], ah[1], b1[2], b1[3]);
            // term lh
            mma_tf32(c[0][n0], al[0], b0[0], b0[1]);
            mma_tf32(c[1][n0], al[1], b0[0], b0[1]);
            mma_tf32(c[0][n1], al[0], b1[0], b1[1]);
            mma_tf32(c[1][n1], al[1], b1[0], b1[1]);
            #pragma unroll
            for (int s = 0; s < 4; s++) { b0[s] = p0[s]; b1[s] = p1[s]; }
        }

        #pragma unroll
        for (int mt = 0; mt < 2; mt++) {
            ra[mt][0] = rb[mt][0];
            ra[mt][1] = rb[mt][1];
        }
    }

    // ---- sB dead; alias with h1 and write C frags ----
    __syncthreads();
    #pragma unroll
    for (int mt = 0; mt < 2; mt++) {
        int row0 = wid * 32 + mt * 16 + g;
        #pragma unroll
        for (int nt = 0; nt < 8; nt++) {
            int col = nt * 8 + tig * 2;
            float2 v0; v0.x = c[mt][nt][0]; v0.y = c[mt][nt][1];
            float2 v1; v1.x = c[mt][nt][2]; v1.y = c[mt][nt][3];
            *(float2*)&sh1[row0 * H1_PITCH + col] = v0;
            *(float2*)&sh1[(row0 + 8) * H1_PITCH + col] = v1;
        }
    }
    __syncthreads();

    // ---- per-thread fp32 tail: row = tid ----
    const float* sb1 = sm + B1_OFF_F;
    const float* sw2 = sm + W2_OFF_F;
    const float* sb2 = sm + B2_OFF_F;
    const float* sw3 = sm + W3_OFF_F;
    const float* sb3 = sm + B3_OFF_F;
    const float* hrow = &sh1[tid * H1_PITCH];

    float h2[16];
    #pragma unroll
    for (int j = 0; j < 16; j++) h2[j] = sb2[j];
    #pragma unroll
    for (int i4 = 0; i4 < 16; i4++) {
        float4 hv = *(const float4*)&hrow[i4 * 4];
        float h0 = fmaxf(hv.x + sb1[i4 * 4 + 0], 0.0f);
        float h1v = fmaxf(hv.y + sb1[i4 * 4 + 1], 0.0f);
        float h2v = fmaxf(hv.z + sb1[i4 * 4 + 2], 0.0f);
        float h3 = fmaxf(hv.w + sb1[i4 * 4 + 3], 0.0f);
        const float* wr0 = &sw2[(i4 * 4 + 0) * 16];
        const float* wr1 = &sw2[(i4 * 4 + 1) * 16];
        const float* wr2 = &sw2[(i4 * 4 + 2) * 16];
        const float* wr3 = &sw2[(i4 * 4 + 3) * 16];
        #pragma unroll
        for (int j = 0; j < 16; j++) {
            float t = fmaf(h0, wr0[j], h2[j]);
            t = fmaf(h1v, wr1[j], t);
            t = fmaf(h2v, wr2[j], t);
            h2[j] = fmaf(h3, wr3[j], t);
        }
    }
    #pragma unroll
    for (int j = 0; j < 16; j++) h2[j] = tanhf(h2[j]);

    float lg[4];
    #pragma unroll
    for (int j = 0; j < 4; j++) lg[j] = sb3[j];
    #pragma unroll
    for (int i = 0; i < 16; i++) {
        float h = h2[i];
        const float* wr = &sw3[i * 4];
        #pragma unroll
        for (int j = 0; j < 4; j++) lg[j] = fmaf(h, wr[j], lg[j]);
    }

    float e0 = __expf(lg[0]);
    float e1 = __expf(lg[1]);
    float e2 = __expf(lg[2]);
    float e3 = __expf(lg[3]);

    const size_t row = (size_t)blockIdx.x * ROWS_CTA + tid;
    float4 ev; ev.x = e0; ev.y = e1; ev.z = e2; ev.w = e3;
    ((float4*)out)[row] = ev;

    // deterministic block partial sum
    float* red = sm + RED_OFF_F;
    red[tid] = (e0 + e1) + (e2 + e3);
    __syncthreads();
    #pragma unroll
    for (int off = TPB / 2; off > 0; off >>= 1) {
        if (tid < off) red[tid] += red[tid + off];
        __syncthreads();
    }
    if (tid == 0) g_partials[blockIdx.x] = red[0];
}

// fused: every block deterministically reduces the 256 partials (identical
// order -> identical result), then scales its slice of out.
__global__ void scale_kernel(float* __restrict__ out)
{
    __shared__ float red[NBLK];
    const int tid = threadIdx.x;   // 256 threads
    red[tid] = g_partials[tid];
    __syncthreads();
    #pragma unroll
    for (int off = NBLK / 2; off > 0; off >>= 1) {
        if (tid < off) red[tid] += red[tid + off];
        __syncthreads();
    }
    const float inv = 1.0f / red[0];

    const int i = blockIdx.x * blockDim.x + tid;  // one float4 per thread
    float4 v = ((float4*)out)[i];
    v.x *= inv; v.y *= inv; v.z *= inv; v.w *= inv;
    ((float4*)out)[i] = v;
}

extern "C" void kernel_launch(void* const* d_in, const int* in_sizes, int n_in,
                              void* d_out, int out_size)
{
    const float* x  = (const float*)d_in[0];
    const float* w1 = (const float*)d_in[1];
    const float* b1 = (const float*)d_in[2];
    const float* w2 = (const float*)d_in[3];
    const float* b2 = (const float*)d_in[4];
    const float* w3 = (const float*)d_in[5];
    const float* b3 = (const float*)d_in[6];
    float* out = (float*)d_out;

    const size_t smem = SM_FLOATS * sizeof(float);
    cudaFuncSetAttribute(mlp_kernel, cudaFuncAttributeMaxDynamicSharedMemorySize, (int)smem);

    mlp_kernel<<<NBLK, TPB, smem>>>(x, w1, b1, w2, b2, w3, b3, out);
    scale_kernel<<<(B_ROWS * 4) / (4 * 256), 256>>>(out);
}